// round 10
// baseline (speedup 1.0000x reference)
#include <cuda_runtime.h>
#include <cuda_bf16.h>
#include <math.h>
#include <stdint.h>

#define DD 1024
#define HEADS 16
#define DH 64
#define B_LAT 9
#define B_X 8
#define N_KV 256
#define N_Q 64
#define KV_PER_B (N_KV + N_Q)       /* 320  */
#define ROWS_X (B_X * N_KV)         /* 2048 */
#define ROWS_LAT (B_LAT * N_Q)      /* 576  */
#define ROWS_KV (B_X * KV_PER_B)    /* 2560 */
#define EPS 1e-5f
#define NCHUNK 8
#define NPART (B_LAT * HEADS * NCHUNK)   /* 1152 */
#define K3 3072                     /* split-bf16 extended K = 3*1024 */

// ---------------- scratch (static device globals; no allocation) ----------------
__device__ float g_q[ROWS_LAT * DD];
__device__ float g_kv[ROWS_KV * 2 * DD];
__device__ float g_pO[(size_t)NPART * 64 * 64];
__device__ float g_pm[NPART * 64];
__device__ float g_pl[NPART * 64];
// split-bf16 operands: A3 = [Ah | Ah | Al] rows [M,3072]; W3 = [Wh | Wl | Wh] rows [N,3072]
__device__ __nv_bfloat16 g_a3kv[(size_t)ROWS_KV * K3];
__device__ __nv_bfloat16 g_a3small[(size_t)ROWS_LAT * K3];   // lnlat splits, later ao splits
__device__ __nv_bfloat16 g_w3q[(size_t)DD * K3];
__device__ __nv_bfloat16 g_w3kv[(size_t)(2 * DD) * K3];
__device__ __nv_bfloat16 g_w3out[(size_t)DD * K3];

// ---------------- PTX helpers (base ISA only: sm_80-compatible) ----------------
__device__ __forceinline__ uint32_t smem_u32(const void* p) {
    uint32_t a;
    asm("{ .reg .u64 t; cvta.to.shared.u64 t, %1; cvt.u32.u64 %0, t; }" : "=r"(a) : "l"(p));
    return a;
}
__device__ __forceinline__ void cp_async16(uint32_t s, const void* g, int sz) {
    asm volatile("cp.async.cg.shared.global [%0], [%1], 16, %2;"
                 :: "r"(s), "l"(g), "r"(sz) : "memory");
}
#define CP_COMMIT()  asm volatile("cp.async.commit_group;" ::: "memory")
#define CP_WAIT0()   asm volatile("cp.async.wait_group 0;" ::: "memory")
#define CP_WAIT1()   asm volatile("cp.async.wait_group 1;" ::: "memory")

__device__ __forceinline__ void ldm_x4(uint32_t* r, uint32_t a) {
    asm volatile("ldmatrix.sync.aligned.m8n8.x4.shared.b16 {%0,%1,%2,%3}, [%4];"
                 : "=r"(r[0]), "=r"(r[1]), "=r"(r[2]), "=r"(r[3]) : "r"(a));
}
__device__ __forceinline__ void mma_bf16(float* d, const uint32_t* a, uint32_t b0, uint32_t b1) {
    asm volatile("mma.sync.aligned.m16n8k16.row.col.f32.bf16.bf16.f32 "
                 "{%0,%1,%2,%3}, {%4,%5,%6,%7}, {%8,%9}, {%0,%1,%2,%3};"
                 : "+f"(d[0]), "+f"(d[1]), "+f"(d[2]), "+f"(d[3])
                 : "r"(a[0]), "r"(a[1]), "r"(a[2]), "r"(a[3]), "r"(b0), "r"(b1));
}

// store 4 fp32 values as split-bf16 triple at dst[0], dst[1024], dst[2048]
__device__ __forceinline__ void store_split4_A(__nv_bfloat16* dst, float4 v) {
    __nv_bfloat16 h0 = __float2bfloat16(v.x), h1 = __float2bfloat16(v.y);
    __nv_bfloat16 h2 = __float2bfloat16(v.z), h3 = __float2bfloat16(v.w);
    __nv_bfloat16 l0 = __float2bfloat16(v.x - __bfloat162float(h0));
    __nv_bfloat16 l1 = __float2bfloat16(v.y - __bfloat162float(h1));
    __nv_bfloat16 l2 = __float2bfloat16(v.z - __bfloat162float(h2));
    __nv_bfloat16 l3 = __float2bfloat16(v.w - __bfloat162float(h3));
    __nv_bfloat162 H0 = {h0, h1}, H1 = {h2, h3}, L0 = {l0, l1}, L1 = {l2, l3};
    *(__nv_bfloat162*)&dst[0]        = H0; *(__nv_bfloat162*)&dst[2]        = H1;
    *(__nv_bfloat162*)&dst[1024]     = H0; *(__nv_bfloat162*)&dst[1026]     = H1;
    *(__nv_bfloat162*)&dst[2048]     = L0; *(__nv_bfloat162*)&dst[2050]     = L1;
}

// ---------------- LayerNorm: one block per row, 256 threads; emits split-bf16 ----------------
__global__ void ln_kernel(const float* __restrict__ x, const float* __restrict__ lat,
                          const float* __restrict__ g1, const float* __restrict__ b1,
                          const float* __restrict__ g2, const float* __restrict__ b2) {
    int row = blockIdx.x;
    const float *src, *g, *b;
    __nv_bfloat16 *dst0, *dst1 = nullptr;
    if (row < ROWS_X) {
        int bb = row / N_KV, n = row % N_KV;
        src = x + (size_t)row * DD; g = g1; b = b1;
        dst0 = g_a3kv + (size_t)(bb * KV_PER_B + n) * K3;
    } else {
        int lr = row - ROWS_X;
        int bb = lr / N_Q, n = lr % N_Q;
        src = lat + (size_t)lr * DD; g = g2; b = b2;
        dst0 = g_a3small + (size_t)lr * K3;
        if (bb < B_X) dst1 = g_a3kv + (size_t)(bb * KV_PER_B + N_KV + n) * K3;
    }
    int tid = threadIdx.x;
    float4 v = ((const float4*)src)[tid];
    float s  = v.x + v.y + v.z + v.w;
    float ss = v.x*v.x + v.y*v.y + v.z*v.z + v.w*v.w;
    #pragma unroll
    for (int o = 16; o; o >>= 1) {
        s  += __shfl_xor_sync(0xFFFFFFFFu, s,  o);
        ss += __shfl_xor_sync(0xFFFFFFFFu, ss, o);
    }
    __shared__ float sb[8], ssb[8];
    int wid = tid >> 5, lane = tid & 31;
    if (lane == 0) { sb[wid] = s; ssb[wid] = ss; }
    __syncthreads();
    float ts = 0.f, tss = 0.f;
    #pragma unroll
    for (int i = 0; i < 8; i++) { ts += sb[i]; tss += ssb[i]; }
    float mean = ts * (1.0f / DD);
    float var  = tss * (1.0f / DD) - mean * mean;
    float inv  = rsqrtf(var + EPS);
    float4 gg = ((const float4*)g)[tid];
    float4 bb4 = ((const float4*)b)[tid];
    float4 o;
    o.x = (v.x - mean) * inv * gg.x + bb4.x;
    o.y = (v.y - mean) * inv * gg.y + bb4.y;
    o.z = (v.z - mean) * inv * gg.z + bb4.z;
    o.w = (v.w - mean) * inv * gg.w + bb4.w;
    store_split4_A(dst0 + tid * 4, o);
    if (dst1) store_split4_A(dst1 + tid * 4, o);
}

// ---------------- merged W conversions: all three weights in one launch ----------------
__global__ void convW_all(const float* __restrict__ Wq, const float* __restrict__ Wkv,
                          const float* __restrict__ Wout) {
    int t = blockIdx.x;
    const float* W; __nv_bfloat16* dst; int N; int lt;
    if (t < 1024)      { W = Wq;   dst = g_w3q;   N = DD;     lt = t; }
    else if (t < 3072) { W = Wkv;  dst = g_w3kv;  N = 2 * DD; lt = t - 1024; }
    else               { W = Wout; dst = g_w3out; N = DD;     lt = t - 3072; }
    int ntiles_x = N / 32;
    int n0 = (lt % ntiles_x) * 32, k0 = (lt / ntiles_x) * 32;

    __shared__ float tt[32][33];
    int tx = threadIdx.x, ty = threadIdx.y;
    #pragma unroll
    for (int j = 0; j < 4; j++)
        tt[ty + j * 8][tx] = W[(size_t)(k0 + ty + j * 8) * N + n0 + tx];
    __syncthreads();
    #pragma unroll
    for (int j = 0; j < 4; j++) {
        int n = n0 + ty + j * 8, k = k0 + tx;
        float a = tt[tx][ty + j * 8];
        __nv_bfloat16 h = __float2bfloat16(a);
        __nv_bfloat16 l = __float2bfloat16(a - __bfloat162float(h));
        size_t o = (size_t)n * K3 + k;
        dst[o] = h; dst[o + 1024] = l; dst[o + 2048] = h;
    }
}

// ---------------- mma.sync bf16 GEMM core: 3-stage cp.async + frag pipelining ----------------
#define GBK 64
#define KST 72
#define ABUF (128 * KST * 2)
#define STAGE (2 * ABUF)
#define NSTAGE 3
#define GEMM_SMEM (NSTAGE * STAGE)           /* 110592 B */
#define NCH (K3 / GBK)                       /* 48 */

__device__ __forceinline__ void gemm_core(const __nv_bfloat16* __restrict__ A3,
                                          const __nv_bfloat16* __restrict__ B3,
                                          float* __restrict__ C,
                                          int M, int N, int br, int bc,
                                          unsigned char* dynsm) {
    int tid = threadIdx.x, wid = tid >> 5, lane = tid & 31;
    int wm = (wid >> 2) * 64;
    int wn = (wid & 3) * 32;

    auto issue = [&](int kb) {
        unsigned char* sb = dynsm + (kb % NSTAGE) * STAGE;
        const __nv_bfloat16* Ab = A3 + kb * GBK;
        const __nv_bfloat16* Bb = B3 + (size_t)bc * K3 + kb * GBK;
        #pragma unroll
        for (int j = 0; j < 4; j++) {
            int idx = tid + j * 256;
            int r = idx >> 3, c8 = idx & 7;
            int gr = br + r; int sz = (gr < M) ? 16 : 0;
            if (gr >= M) gr = M - 1;
            cp_async16(smem_u32(sb + (r * KST + c8 * 8) * 2),
                       Ab + (size_t)gr * K3 + c8 * 8, sz);
            cp_async16(smem_u32(sb + ABUF + (r * KST + c8 * 8) * 2),
                       Bb + (size_t)r * K3 + c8 * 8, 16);
        }
        CP_COMMIT();
    };

    float acc[4][4][4] = {};
    uint32_t fa[2][4][4], fb[2][2][4];

    issue(0);
    issue(1);

    for (int kb = 0; kb < NCH; kb++) {
        if (kb + 1 < NCH) CP_WAIT1(); else CP_WAIT0();
        __syncthreads();                   // stage kb landed; all warps done with kb-1
        if (kb + 2 < NCH) issue(kb + 2);   // overwrites stage of chunk kb-1 (safe)

        const unsigned char* sA = dynsm + (kb % NSTAGE) * STAGE;
        const unsigned char* sB = sA + ABUF;

        // load fragments for ks=0
        #pragma unroll
        for (int mt = 0; mt < 4; mt++) {
            int arow = wm + mt * 16 + (lane & 15);
            ldm_x4(fa[0][mt], smem_u32(sA + (arow * KST + (lane >> 4) * 8) * 2));
        }
        #pragma unroll
        for (int np = 0; np < 2; np++) {
            int nrow = wn + np * 16 + (lane & 7) + ((lane >> 4) << 3);
            ldm_x4(fb[0][np], smem_u32(sB + (nrow * KST + ((lane >> 3) & 1) * 8) * 2));
        }

        #pragma unroll
        for (int ks = 0; ks < 4; ks++) {
            int cb = ks & 1, nb = cb ^ 1;
            if (ks < 3) {
                int k1 = (ks + 1) * 16;
                #pragma unroll
                for (int mt = 0; mt < 4; mt++) {
                    int arow = wm + mt * 16 + (lane & 15);
                    ldm_x4(fa[nb][mt], smem_u32(sA + (arow * KST + k1 + (lane >> 4) * 8) * 2));
                }
                #pragma unroll
                for (int np = 0; np < 2; np++) {
                    int nrow = wn + np * 16 + (lane & 7) + ((lane >> 4) << 3);
                    ldm_x4(fb[nb][np], smem_u32(sB + (nrow * KST + k1 + ((lane >> 3) & 1) * 8) * 2));
                }
            }
            #pragma unroll
            for (int mt = 0; mt < 4; mt++)
                #pragma unroll
                for (int nt = 0; nt < 4; nt++)
                    mma_bf16(acc[mt][nt], fa[cb][mt], fb[cb][nt >> 1][(nt & 1) * 2],
                             fb[cb][nt >> 1][(nt & 1) * 2 + 1]);
        }
    }

    #pragma unroll
    for (int mt = 0; mt < 4; mt++) {
        int r0 = br + wm + mt * 16 + (lane >> 2);
        #pragma unroll
        for (int nt = 0; nt < 4; nt++) {
            int c = bc + wn + nt * 8 + (lane & 3) * 2;
            if (r0 < M)
                *(float2*)&C[(size_t)r0 * N + c] = make_float2(acc[mt][nt][0], acc[mt][nt][1]);
            if (r0 + 8 < M)
                *(float2*)&C[(size_t)(r0 + 8) * N + c] = make_float2(acc[mt][nt][2], acc[mt][nt][3]);
        }
    }
}

// merged Q + KV projection: KV tiles (320) first, then Q tiles (40)
#define KV_TILES 320
#define Q_TILES  40

__global__ __launch_bounds__(256)
void gemm_qkv() {
    extern __shared__ __align__(16) unsigned char dynsm[];
    int bid = blockIdx.x;
    if (bid < KV_TILES) {
        int bx = bid & 15, by = bid >> 4;
        gemm_core(g_a3kv, g_w3kv, g_kv, ROWS_KV, 2 * DD, by * 128, bx * 128, dynsm);
    } else {
        int t = bid - KV_TILES;
        int bx = t & 7, by = t >> 3;
        gemm_core(g_a3small, g_w3q, g_q, ROWS_LAT, DD, by * 128, bx * 128, dynsm);
    }
}

__global__ __launch_bounds__(256)
void gemm_out(float* __restrict__ C) {
    extern __shared__ __align__(16) unsigned char dynsm[];
    gemm_core(g_a3small, g_w3out, C, ROWS_LAT, DD, blockIdx.y * 128, blockIdx.x * 128, dynsm);
}

// ---------------- flash attention: 64-query x 64-key subtiles, split-KV ----------------
#define ASTR 68

__global__ __launch_bounds__(256)
void attn_flash(const int* __restrict__ um_p) {
    int b  = blockIdx.x;
    int qb = b >> 7;
    int h  = (b >> 3) & 15;
    int c  = b & 7;
    int um = *um_p;
    bool single = (um != 0) && (qb < B_X);
    if (single && c != qb) return;   // whole block exits before any barrier

    extern __shared__ float smf[];
    float* Qs = smf;                    // [d][q] pre-scaled
    float* Ks = smf + 64 * ASTR;        // [d][k]
    float* Vs = smf + 2 * 64 * ASTR;    // [k][d]
    float* Ps = smf + 3 * 64 * ASTR;    // [q][k]
    float* mrow = smf + 4 * 64 * ASTR;
    float* lrow = mrow + 64;
    float* arow = mrow + 128;

    int tid = threadIdx.x;
    int ty = tid >> 4, tx = tid & 15;

    #pragma unroll
    for (int it = 0; it < 4; it++) {
        int row = ty + it * 16;
        int col = tx * 4;
        float4 v = *(const float4*)&g_q[(size_t)(qb * 64 + row) * DD + h * DH + col];
        Qs[(col + 0) * ASTR + row] = v.x * 0.125f;
        Qs[(col + 1) * ASTR + row] = v.y * 0.125f;
        Qs[(col + 2) * ASTR + row] = v.z * 0.125f;
        Qs[(col + 3) * ASTR + row] = v.w * 0.125f;
    }
    if (tid < 64) { mrow[tid] = -INFINITY; lrow[tid] = 0.f; }

    float oacc[4][4] = {};
    int ks0 = c * KV_PER_B;

    for (int sub = 0; sub < 5; sub++) {
        int kb = ks0 + sub * 64;
        __syncthreads();
        #pragma unroll
        for (int it = 0; it < 4; it++) {
            int row = ty + it * 16;
            int col = tx * 4;
            const float* base = g_kv + (size_t)(kb + row) * (2 * DD) + h * DH + col;
            float4 kk = *(const float4*)base;
            Ks[(col + 0) * ASTR + row] = kk.x;
            Ks[(col + 1) * ASTR + row] = kk.y;
            Ks[(col + 2) * ASTR + row] = kk.z;
            Ks[(col + 3) * ASTR + row] = kk.w;
            *(float4*)&Vs[row * ASTR + col] = *(const float4*)(base + DD);
        }
        __syncthreads();

        float sacc[4][4] = {};
        #pragma unroll
        for (int d = 0; d < 64; d++) {
            float4 aq = *(const float4*)&Qs[d * ASTR + ty * 4];
            float4 bk = *(const float4*)&Ks[d * ASTR + tx * 4];
            sacc[0][0] += aq.x * bk.x; sacc[0][1] += aq.x * bk.y;
            sacc[0][2] += aq.x * bk.z; sacc[0][3] += aq.x * bk.w;
            sacc[1][0] += aq.y * bk.x; sacc[1][1] += aq.y * bk.y;
            sacc[1][2] += aq.y * bk.z; sacc[1][3] += aq.y * bk.w;
            sacc[2][0] += aq.z * bk.x; sacc[2][1] += aq.z * bk.y;
            sacc[2][2] += aq.z * bk.z; sacc[2][3] += aq.z * bk.w;
            sacc[3][0] += aq.w * bk.x; sacc[3][1] += aq.w * bk.y;
            sacc[3][2] += aq.w * bk.z; sacc[3][3] += aq.w * bk.w;
        }
        #pragma unroll
        for (int i = 0; i < 4; i++)
            #pragma unroll
            for (int j = 0; j < 4; j++)
                Ps[(ty * 4 + i) * ASTR + tx * 4 + j] = sacc[i][j];
        __syncthreads();

        {
            int r = tid >> 2, part = tid & 3;
            float rm = -INFINITY;
            #pragma unroll
            for (int i = 0; i < 16; i++)
                rm = fmaxf(rm, Ps[r * ASTR + part * 16 + i]);
            rm = fmaxf(rm, __shfl_xor_sync(0xFFFFFFFFu, rm, 1));
            rm = fmaxf(rm, __shfl_xor_sync(0xFFFFFFFFu, rm, 2));
            float mo = mrow[r];
            float nm = fmaxf(mo, rm);
            float psum = 0.f;
            #pragma unroll
            for (int i = 0; i < 16; i++) {
                float p = __expf(Ps[r * ASTR + part * 16 + i] - nm);
                Ps[r * ASTR + part * 16 + i] = p;
                psum += p;
            }
            psum += __shfl_xor_sync(0xFFFFFFFFu, psum, 1);
            psum += __shfl_xor_sync(0xFFFFFFFFu, psum, 2);
            if (part == 0) {
                float a = __expf(mo - nm);
                arow[r] = a;
                lrow[r] = lrow[r] * a + psum;
                mrow[r] = nm;
            }
        }
        __syncthreads();

        float al[4];
        #pragma unroll
        for (int i = 0; i < 4; i++) al[i] = arow[ty * 4 + i];
        #pragma unroll
        for (int i = 0; i < 4; i++)
            #pragma unroll
            for (int j = 0; j < 4; j++) oacc[i][j] *= al[i];
        #pragma unroll
        for (int k = 0; k < 64; k++) {
            float4 v4 = *(const float4*)&Vs[k * ASTR + tx * 4];
            float p0 = Ps[(ty * 4 + 0) * ASTR + k];
            float p1 = Ps[(ty * 4 + 1) * ASTR + k];
            float p2 = Ps[(ty * 4 + 2) * ASTR + k];
            float p3 = Ps[(ty * 4 + 3) * ASTR + k];
            oacc[0][0] += p0 * v4.x; oacc[0][1] += p0 * v4.y;
            oacc[0][2] += p0 * v4.z; oacc[0][3] += p0 * v4.w;
            oacc[1][0] += p1 * v4.x; oacc[1][1] += p1 * v4.y;
            oacc[1][2] += p1 * v4.z; oacc[1][3] += p1 * v4.w;
            oacc[2][0] += p2 * v4.x; oacc[2][1] += p2 * v4.y;
            oacc[2][2] += p2 * v4.z; oacc[2][3] += p2 * v4.w;
            oacc[3][0] += p3 * v4.x; oacc[3][1] += p3 * v4.y;
            oacc[3][2] += p3 * v4.z; oacc[3][3] += p3 * v4.w;
        }
    }

    if (single) {
        #pragma unroll
        for (int i = 0; i < 4; i++) {
            float inv = 1.0f / lrow[ty * 4 + i];
            float4 o = make_float4(oacc[i][0] * inv, oacc[i][1] * inv,
                                   oacc[i][2] * inv, oacc[i][3] * inv);
            store_split4_A(g_a3small + (size_t)(qb * 64 + ty * 4 + i) * K3 + h * DH + tx * 4, o);
        }
    } else {
        int pidx = (qb * HEADS + h) * NCHUNK + c;
        #pragma unroll
        for (int i = 0; i < 4; i++) {
            float4 o = make_float4(oacc[i][0], oacc[i][1], oacc[i][2], oacc[i][3]);
            *(float4*)&g_pO[((size_t)pidx * 64 + ty * 4 + i) * 64 + tx * 4] = o;
        }
        if (tid < 64) {
            g_pm[pidx * 64 + tid] = mrow[tid];
            g_pl[pidx * 64 + tid] = lrow[tid];
        }
    }
}

// merge 8 split-KV partials; coarsened: 256 threads = 4 (q,h) pairs per block
__global__ __launch_bounds__(256)
void attn_combine(const int* __restrict__ um_p) {
    int q = blockIdx.x * 4 + (threadIdx.x >> 6);
    int h = blockIdx.y;
    int qb = q >> 6, qq = q & 63;
    int um = *um_p;
    if (um && qb < B_X) return;   // uniform across block (4 consecutive q share qb)
    int d = threadIdx.x & 63;
    int pbase = (qb * HEADS + h) * NCHUNK;
    float mv[NCHUNK], lv[NCHUNK];
    float M = -INFINITY;
    #pragma unroll
    for (int c = 0; c < NCHUNK; c++) {
        mv[c] = g_pm[(pbase + c) * 64 + qq];
        lv[c] = g_pl[(pbase + c) * 64 + qq];
        M = fmaxf(M, mv[c]);
    }
    float L = 0.f, o = 0.f;
    #pragma unroll
    for (int c = 0; c < NCHUNK; c++) {
        float e = __expf(mv[c] - M);
        L += lv[c] * e;
        o += g_pO[((size_t)(pbase + c) * 64 + qq) * 64 + d] * e;
    }
    float r = o / L;
    __nv_bfloat16 hh = __float2bfloat16(r);
    __nv_bfloat16 ll = __float2bfloat16(r - __bfloat162float(hh));
    __nv_bfloat16* dst = g_a3small + (size_t)q * K3 + h * DH + d;
    dst[0] = hh; dst[1024] = hh; dst[2048] = ll;
}

// ---------------- launch ----------------
#define ATTN_SMEM ((4 * 64 * ASTR + 192) * (int)sizeof(float))   /* 70400 B */

extern "C" void kernel_launch(void* const* d_in, const int* in_sizes, int n_in,
                              void* d_out, int out_size) {
    const float* x    = (const float*)d_in[0];
    const float* lat  = (const float*)d_in[1];
    const float* g1   = (const float*)d_in[2];
    const float* b1   = (const float*)d_in[3];
    const float* g2   = (const float*)d_in[4];
    const float* b2   = (const float*)d_in[5];
    const float* Wq   = (const float*)d_in[6];
    const float* Wkv  = (const float*)d_in[7];
    const float* Wout = (const float*)d_in[8];
    const int*   um   = (const int*)d_in[9];
    float* out = (float*)d_out;

    cudaFuncSetAttribute(gemm_qkv,   cudaFuncAttributeMaxDynamicSharedMemorySize, GEMM_SMEM);
    cudaFuncSetAttribute(gemm_out,   cudaFuncAttributeMaxDynamicSharedMemorySize, GEMM_SMEM);
    cudaFuncSetAttribute(attn_flash, cudaFuncAttributeMaxDynamicSharedMemorySize, ATTN_SMEM);

    // 1. LayerNorms -> split-bf16 GEMM operands directly
    ln_kernel<<<ROWS_X + ROWS_LAT, 256>>>(x, lat, g1, b1, g2, b2);

    // 2. all weight conversions, one launch
    convW_all<<<4096, dim3(32, 8)>>>(Wq, Wkv, Wout);

    // 3. Q + KV projections, one launch (3-stage pipelined GEMM core)
    gemm_qkv<<<KV_TILES + Q_TILES, 256, GEMM_SMEM>>>();

    // 4. flash attention (64-key subtiles) + coarsened combine; outputs split-bf16
    attn_flash<<<NPART, 256, ATTN_SMEM>>>(um);
    attn_combine<<<dim3(ROWS_LAT / 4, HEADS), 256>>>(um);

    // 5. output projection
    gemm_out<<<dim3(DD / 128, (ROWS_LAT + 127) / 128), 256, GEMM_SMEM>>>(out);
}

// round 11
// speedup vs baseline: 1.1081x; 1.1081x over previous
#include <cuda_runtime.h>
#include <cuda_bf16.h>
#include <math.h>
#include <stdint.h>

#define DD 1024
#define HEADS 16
#define DH 64
#define B_LAT 9
#define B_X 8
#define N_KV 256
#define N_Q 64
#define KV_PER_B (N_KV + N_Q)       /* 320  */
#define ROWS_X (B_X * N_KV)         /* 2048 */
#define ROWS_LAT (B_LAT * N_Q)      /* 576  */
#define ROWS_KV (B_X * KV_PER_B)    /* 2560 */
#define EPS 1e-5f
#define NSUB 40                     /* 2560/64 key subtiles */
#define NPART40 (B_LAT * HEADS * NSUB)   /* 5760 */
#define K3 3072                     /* split-bf16 extended K = 3*1024 */

// ---------------- scratch (static device globals; no allocation) ----------------
__device__ float g_q[ROWS_LAT * DD];
__device__ float g_kv[ROWS_KV * 2 * DD];
__device__ float g_pO[(size_t)NPART40 * 64 * 64];   /* 94.4 MB */
__device__ float g_pm[NPART40 * 64];
__device__ float g_pl[NPART40 * 64];
// split-bf16 operands: A3 = [Ah | Ah | Al] rows [M,3072]; W3 = [Wh | Wl | Wh] rows [N,3072]
__device__ __nv_bfloat16 g_a3kv[(size_t)ROWS_KV * K3];
__device__ __nv_bfloat16 g_a3small[(size_t)ROWS_LAT * K3];   // lnlat splits, later ao splits
__device__ __nv_bfloat16 g_w3q[(size_t)DD * K3];
__device__ __nv_bfloat16 g_w3kv[(size_t)(2 * DD) * K3];
__device__ __nv_bfloat16 g_w3out[(size_t)DD * K3];

// ---------------- PTX helpers (base ISA only: sm_80-compatible) ----------------
__device__ __forceinline__ uint32_t smem_u32(const void* p) {
    uint32_t a;
    asm("{ .reg .u64 t; cvta.to.shared.u64 t, %1; cvt.u32.u64 %0, t; }" : "=r"(a) : "l"(p));
    return a;
}
__device__ __forceinline__ void cp_async16(uint32_t s, const void* g, int sz) {
    asm volatile("cp.async.cg.shared.global [%0], [%1], 16, %2;"
                 :: "r"(s), "l"(g), "r"(sz) : "memory");
}
#define CP_COMMIT()  asm volatile("cp.async.commit_group;" ::: "memory")
#define CP_WAIT0()   asm volatile("cp.async.wait_group 0;" ::: "memory")

__device__ __forceinline__ void ldm_x4(uint32_t* r, uint32_t a) {
    asm volatile("ldmatrix.sync.aligned.m8n8.x4.shared.b16 {%0,%1,%2,%3}, [%4];"
                 : "=r"(r[0]), "=r"(r[1]), "=r"(r[2]), "=r"(r[3]) : "r"(a));
}
__device__ __forceinline__ void mma_bf16(float* d, const uint32_t* a, uint32_t b0, uint32_t b1) {
    asm volatile("mma.sync.aligned.m16n8k16.row.col.f32.bf16.bf16.f32 "
                 "{%0,%1,%2,%3}, {%4,%5,%6,%7}, {%8,%9}, {%0,%1,%2,%3};"
                 : "+f"(d[0]), "+f"(d[1]), "+f"(d[2]), "+f"(d[3])
                 : "r"(a[0]), "r"(a[1]), "r"(a[2]), "r"(a[3]), "r"(b0), "r"(b1));
}

// store 4 fp32 values as split-bf16 triple at dst[0], dst[1024], dst[2048]
__device__ __forceinline__ void store_split4_A(__nv_bfloat16* dst, float4 v) {
    __nv_bfloat16 h0 = __float2bfloat16(v.x), h1 = __float2bfloat16(v.y);
    __nv_bfloat16 h2 = __float2bfloat16(v.z), h3 = __float2bfloat16(v.w);
    __nv_bfloat16 l0 = __float2bfloat16(v.x - __bfloat162float(h0));
    __nv_bfloat16 l1 = __float2bfloat16(v.y - __bfloat162float(h1));
    __nv_bfloat16 l2 = __float2bfloat16(v.z - __bfloat162float(h2));
    __nv_bfloat16 l3 = __float2bfloat16(v.w - __bfloat162float(h3));
    __nv_bfloat162 H0 = {h0, h1}, H1 = {h2, h3}, L0 = {l0, l1}, L1 = {l2, l3};
    *(__nv_bfloat162*)&dst[0]        = H0; *(__nv_bfloat162*)&dst[2]        = H1;
    *(__nv_bfloat162*)&dst[1024]     = H0; *(__nv_bfloat162*)&dst[1026]     = H1;
    *(__nv_bfloat162*)&dst[2048]     = L0; *(__nv_bfloat162*)&dst[2050]     = L1;
}

// ---------------- LayerNorm: one block per row, 256 threads; emits split-bf16 ----------------
__global__ void ln_kernel(const float* __restrict__ x, const float* __restrict__ lat,
                          const float* __restrict__ g1, const float* __restrict__ b1,
                          const float* __restrict__ g2, const float* __restrict__ b2) {
    int row = blockIdx.x;
    const float *src, *g, *b;
    __nv_bfloat16 *dst0, *dst1 = nullptr;
    if (row < ROWS_X) {
        int bb = row / N_KV, n = row % N_KV;
        src = x + (size_t)row * DD; g = g1; b = b1;
        dst0 = g_a3kv + (size_t)(bb * KV_PER_B + n) * K3;
    } else {
        int lr = row - ROWS_X;
        int bb = lr / N_Q, n = lr % N_Q;
        src = lat + (size_t)lr * DD; g = g2; b = b2;
        dst0 = g_a3small + (size_t)lr * K3;
        if (bb < B_X) dst1 = g_a3kv + (size_t)(bb * KV_PER_B + N_KV + n) * K3;
    }
    int tid = threadIdx.x;
    float4 v = ((const float4*)src)[tid];
    float s  = v.x + v.y + v.z + v.w;
    float ss = v.x*v.x + v.y*v.y + v.z*v.z + v.w*v.w;
    #pragma unroll
    for (int o = 16; o; o >>= 1) {
        s  += __shfl_xor_sync(0xFFFFFFFFu, s,  o);
        ss += __shfl_xor_sync(0xFFFFFFFFu, ss, o);
    }
    __shared__ float sb[8], ssb[8];
    int wid = tid >> 5, lane = tid & 31;
    if (lane == 0) { sb[wid] = s; ssb[wid] = ss; }
    __syncthreads();
    float ts = 0.f, tss = 0.f;
    #pragma unroll
    for (int i = 0; i < 8; i++) { ts += sb[i]; tss += ssb[i]; }
    float mean = ts * (1.0f / DD);
    float var  = tss * (1.0f / DD) - mean * mean;
    float inv  = rsqrtf(var + EPS);
    float4 gg = ((const float4*)g)[tid];
    float4 bb4 = ((const float4*)b)[tid];
    float4 o;
    o.x = (v.x - mean) * inv * gg.x + bb4.x;
    o.y = (v.y - mean) * inv * gg.y + bb4.y;
    o.z = (v.z - mean) * inv * gg.z + bb4.z;
    o.w = (v.w - mean) * inv * gg.w + bb4.w;
    store_split4_A(dst0 + tid * 4, o);
    if (dst1) store_split4_A(dst1 + tid * 4, o);
}

// ---------------- merged W conversions: all three weights in one launch ----------------
__global__ void convW_all(const float* __restrict__ Wq, const float* __restrict__ Wkv,
                          const float* __restrict__ Wout) {
    int t = blockIdx.x;
    const float* W; __nv_bfloat16* dst; int N; int lt;
    if (t < 1024)      { W = Wq;   dst = g_w3q;   N = DD;     lt = t; }
    else if (t < 3072) { W = Wkv;  dst = g_w3kv;  N = 2 * DD; lt = t - 1024; }
    else               { W = Wout; dst = g_w3out; N = DD;     lt = t - 3072; }
    int ntiles_x = N / 32;
    int n0 = (lt % ntiles_x) * 32, k0 = (lt / ntiles_x) * 32;

    __shared__ float tt[32][33];
    int tx = threadIdx.x, ty = threadIdx.y;
    #pragma unroll
    for (int j = 0; j < 4; j++)
        tt[ty + j * 8][tx] = W[(size_t)(k0 + ty + j * 8) * N + n0 + tx];
    __syncthreads();
    #pragma unroll
    for (int j = 0; j < 4; j++) {
        int n = n0 + ty + j * 8, k = k0 + tx;
        float a = tt[tx][ty + j * 8];
        __nv_bfloat16 h = __float2bfloat16(a);
        __nv_bfloat16 l = __float2bfloat16(a - __bfloat162float(h));
        size_t o = (size_t)n * K3 + k;
        dst[o] = h; dst[o + 1024] = l; dst[o + 2048] = h;
    }
}

// ---------------- mma.sync bf16 GEMM core (R9 proven 2-stage version) ----------------
#define GBK 64
#define KST 72
#define ABUF (128 * KST * 2)
#define STAGE (2 * ABUF)
#define GEMM_SMEM (2 * STAGE)                /* 73728 B */
#define NCH (K3 / GBK)                       /* 48 */

__device__ __forceinline__ void gemm_core(const __nv_bfloat16* __restrict__ A3,
                                          const __nv_bfloat16* __restrict__ B3,
                                          float* __restrict__ C,
                                          int M, int N, int br, int bc,
                                          unsigned char* dynsm) {
    int tid = threadIdx.x, wid = tid >> 5, lane = tid & 31;
    int wm = (wid >> 2) * 64;
    int wn = (wid & 3) * 32;

    auto issue = [&](int kb, int buf) {
        unsigned char* sb = dynsm + buf * STAGE;
        const __nv_bfloat16* Ab = A3 + kb * GBK;
        const __nv_bfloat16* Bb = B3 + (size_t)bc * K3 + kb * GBK;
        #pragma unroll
        for (int j = 0; j < 4; j++) {
            int idx = tid + j * 256;
            int r = idx >> 3, c8 = idx & 7;
            int gr = br + r; int sz = (gr < M) ? 16 : 0;
            if (gr >= M) gr = M - 1;
            cp_async16(smem_u32(sb + (r * KST + c8 * 8) * 2),
                       Ab + (size_t)gr * K3 + c8 * 8, sz);
            cp_async16(smem_u32(sb + ABUF + (r * KST + c8 * 8) * 2),
                       Bb + (size_t)r * K3 + c8 * 8, 16);
        }
        CP_COMMIT();
    };

    float acc[4][4][4] = {};

    issue(0, 0);
    CP_WAIT0();
    __syncthreads();

    for (int kb = 0; kb < NCH; kb++) {
        int cur = kb & 1;
        if (kb + 1 < NCH) issue(kb + 1, cur ^ 1);

        const unsigned char* sA = dynsm + cur * STAGE;
        const unsigned char* sB = sA + ABUF;
        #pragma unroll
        for (int ks = 0; ks < 4; ks++) {
            int k0 = ks * 16;
            uint32_t a[4][4];
            #pragma unroll
            for (int mt = 0; mt < 4; mt++) {
                int arow = wm + mt * 16 + (lane & 15);
                int acol = k0 + (lane >> 4) * 8;
                ldm_x4(a[mt], smem_u32(sA + (arow * KST + acol) * 2));
            }
            uint32_t b[2][4];
            #pragma unroll
            for (int np = 0; np < 2; np++) {
                int nrow = wn + np * 16 + (lane & 7) + ((lane >> 4) << 3);
                int kcol = k0 + ((lane >> 3) & 1) * 8;
                ldm_x4(b[np], smem_u32(sB + (nrow * KST + kcol) * 2));
            }
            #pragma unroll
            for (int mt = 0; mt < 4; mt++)
                #pragma unroll
                for (int nt = 0; nt < 4; nt++)
                    mma_bf16(acc[mt][nt], a[mt], b[nt >> 1][(nt & 1) * 2],
                             b[nt >> 1][(nt & 1) * 2 + 1]);
        }
        if (kb + 1 < NCH) CP_WAIT0();
        __syncthreads();
    }

    #pragma unroll
    for (int mt = 0; mt < 4; mt++) {
        int r0 = br + wm + mt * 16 + (lane >> 2);
        #pragma unroll
        for (int nt = 0; nt < 4; nt++) {
            int c = bc + wn + nt * 8 + (lane & 3) * 2;
            if (r0 < M)
                *(float2*)&C[(size_t)r0 * N + c] = make_float2(acc[mt][nt][0], acc[mt][nt][1]);
            if (r0 + 8 < M)
                *(float2*)&C[(size_t)(r0 + 8) * N + c] = make_float2(acc[mt][nt][2], acc[mt][nt][3]);
        }
    }
}

// merged Q + KV projection: KV tiles (320) first, then Q tiles (40)
#define KV_TILES 320
#define Q_TILES  40

__global__ __launch_bounds__(256)
void gemm_qkv() {
    extern __shared__ __align__(16) unsigned char dynsm[];
    int bid = blockIdx.x;
    if (bid < KV_TILES) {
        int bx = bid & 15, by = bid >> 4;
        gemm_core(g_a3kv, g_w3kv, g_kv, ROWS_KV, 2 * DD, by * 128, bx * 128, dynsm);
    } else {
        int t = bid - KV_TILES;
        int bx = t & 7, by = t >> 3;
        gemm_core(g_a3small, g_w3q, g_q, ROWS_LAT, DD, by * 128, bx * 128, dynsm);
    }
}

__global__ __launch_bounds__(256)
void gemm_out(float* __restrict__ C) {
    extern __shared__ __align__(16) unsigned char dynsm[];
    gemm_core(g_a3small, g_w3out, C, ROWS_LAT, DD, blockIdx.y * 128, blockIdx.x * 128, dynsm);
}

// ---------------- attention: one block per 64-key subtile, single-pass softmax ----------------
// grid (s 0..39, h 0..15, qb 0..8). Masked qb<8: active only s<5 with keys
// [qb*320 + s*64, +64). qb==8 / unmasked: keys [s*64, +64). Each block writes an
// (m, l, unnormalized O) partial; attn_combine merges 5 or 40 partials exactly.
#define ASTR 68

__global__ __launch_bounds__(256)
void attn_part(const int* __restrict__ um_p) {
    int s  = blockIdx.x;
    int h  = blockIdx.y;
    int qb = blockIdx.z;
    int um = *um_p;
    bool masked = (um != 0) && (qb < B_X);
    if (masked && s >= 5) return;   // whole block exits before any barrier
    int kbase = masked ? (qb * KV_PER_B + s * 64) : (s * 64);

    extern __shared__ float smf[];
    float* Qs = smf;                    // [d][q] pre-scaled
    float* Ks = smf + 64 * ASTR;        // [d][k]
    float* Vs = smf + 2 * 64 * ASTR;    // [k][d]
    float* Ps = smf + 3 * 64 * ASTR;    // [q][k]
    float* mrow = smf + 4 * 64 * ASTR;  // [64]
    float* lrow = mrow + 64;

    int tid = threadIdx.x;
    int ty = tid >> 4, tx = tid & 15;

    // load Q (transposed, scale folded) + K (transposed) + V (row-major)
    #pragma unroll
    for (int it = 0; it < 4; it++) {
        int row = ty + it * 16;
        int col = tx * 4;
        float4 v = *(const float4*)&g_q[(size_t)(qb * 64 + row) * DD + h * DH + col];
        Qs[(col + 0) * ASTR + row] = v.x * 0.125f;
        Qs[(col + 1) * ASTR + row] = v.y * 0.125f;
        Qs[(col + 2) * ASTR + row] = v.z * 0.125f;
        Qs[(col + 3) * ASTR + row] = v.w * 0.125f;
        const float* base = g_kv + (size_t)(kbase + row) * (2 * DD) + h * DH + col;
        float4 kk = *(const float4*)base;
        Ks[(col + 0) * ASTR + row] = kk.x;
        Ks[(col + 1) * ASTR + row] = kk.y;
        Ks[(col + 2) * ASTR + row] = kk.z;
        Ks[(col + 3) * ASTR + row] = kk.w;
        *(float4*)&Vs[row * ASTR + col] = *(const float4*)(base + DD);
    }
    __syncthreads();

    // S = Q K^T (thread: 4q x 4k)
    float sacc[4][4] = {};
    #pragma unroll
    for (int d = 0; d < 64; d++) {
        float4 aq = *(const float4*)&Qs[d * ASTR + ty * 4];
        float4 bk = *(const float4*)&Ks[d * ASTR + tx * 4];
        sacc[0][0] += aq.x * bk.x; sacc[0][1] += aq.x * bk.y;
        sacc[0][2] += aq.x * bk.z; sacc[0][3] += aq.x * bk.w;
        sacc[1][0] += aq.y * bk.x; sacc[1][1] += aq.y * bk.y;
        sacc[1][2] += aq.y * bk.z; sacc[1][3] += aq.y * bk.w;
        sacc[2][0] += aq.z * bk.x; sacc[2][1] += aq.z * bk.y;
        sacc[2][2] += aq.z * bk.z; sacc[2][3] += aq.z * bk.w;
        sacc[3][0] += aq.w * bk.x; sacc[3][1] += aq.w * bk.y;
        sacc[3][2] += aq.w * bk.z; sacc[3][3] += aq.w * bk.w;
    }
    #pragma unroll
    for (int i = 0; i < 4; i++)
        #pragma unroll
        for (int j = 0; j < 4; j++)
            Ps[(ty * 4 + i) * ASTR + tx * 4 + j] = sacc[i][j];
    __syncthreads();

    // single-pass softmax: 4 threads per row, 16 cols each
    {
        int r = tid >> 2, part = tid & 3;
        float rm = -INFINITY;
        #pragma unroll
        for (int i = 0; i < 16; i++)
            rm = fmaxf(rm, Ps[r * ASTR + part * 16 + i]);
        rm = fmaxf(rm, __shfl_xor_sync(0xFFFFFFFFu, rm, 1));
        rm = fmaxf(rm, __shfl_xor_sync(0xFFFFFFFFu, rm, 2));
        float psum = 0.f;
        #pragma unroll
        for (int i = 0; i < 16; i++) {
            float p = __expf(Ps[r * ASTR + part * 16 + i] - rm);
            Ps[r * ASTR + part * 16 + i] = p;
            psum += p;
        }
        psum += __shfl_xor_sync(0xFFFFFFFFu, psum, 1);
        psum += __shfl_xor_sync(0xFFFFFFFFu, psum, 2);
        if (part == 0) { mrow[r] = rm; lrow[r] = psum; }
    }
    __syncthreads();

    // O = P V (unnormalized), thread: 4q x 4d
    float oacc[4][4] = {};
    #pragma unroll
    for (int k = 0; k < 64; k++) {
        float4 v4 = *(const float4*)&Vs[k * ASTR + tx * 4];
        float p0 = Ps[(ty * 4 + 0) * ASTR + k];
        float p1 = Ps[(ty * 4 + 1) * ASTR + k];
        float p2 = Ps[(ty * 4 + 2) * ASTR + k];
        float p3 = Ps[(ty * 4 + 3) * ASTR + k];
        oacc[0][0] += p0 * v4.x; oacc[0][1] += p0 * v4.y;
        oacc[0][2] += p0 * v4.z; oacc[0][3] += p0 * v4.w;
        oacc[1][0] += p1 * v4.x; oacc[1][1] += p1 * v4.y;
        oacc[1][2] += p1 * v4.z; oacc[1][3] += p1 * v4.w;
        oacc[2][0] += p2 * v4.x; oacc[2][1] += p2 * v4.y;
        oacc[2][2] += p2 * v4.z; oacc[2][3] += p2 * v4.w;
        oacc[3][0] += p3 * v4.x; oacc[3][1] += p3 * v4.y;
        oacc[3][2] += p3 * v4.z; oacc[3][3] += p3 * v4.w;
    }

    int pidx = (qb * HEADS + h) * NSUB + s;
    #pragma unroll
    for (int i = 0; i < 4; i++) {
        float4 o = make_float4(oacc[i][0], oacc[i][1], oacc[i][2], oacc[i][3]);
        *(float4*)&g_pO[((size_t)pidx * 64 + ty * 4 + i) * 64 + tx * 4] = o;
    }
    if (tid < 64) {
        g_pm[pidx * 64 + tid] = mrow[tid];
        g_pl[pidx * 64 + tid] = lrow[tid];
    }
}

// merge partials per (q,h) row: 5 (masked, block qb<8) or 40 (dense); streaming
__global__ __launch_bounds__(256)
void attn_combine(const int* __restrict__ um_p) {
    int q = blockIdx.x * 4 + (threadIdx.x >> 6);
    int h = blockIdx.y;
    int qb = q >> 6, qq = q & 63;
    int um = *um_p;
    bool masked = (um != 0) && (qb < B_X);
    int ns = masked ? 5 : NSUB;
    int d = threadIdx.x & 63;
    int pbase = (qb * HEADS + h) * NSUB;

    float M = -INFINITY;
    for (int c = 0; c < ns; c++)
        M = fmaxf(M, g_pm[(pbase + c) * 64 + qq]);
    float L = 0.f, o = 0.f;
    for (int c = 0; c < ns; c++) {
        float e = __expf(g_pm[(pbase + c) * 64 + qq] - M);
        L += g_pl[(pbase + c) * 64 + qq] * e;
        o += g_pO[((size_t)(pbase + c) * 64 + qq) * 64 + d] * e;
    }
    float r = o / L;
    __nv_bfloat16 hh = __float2bfloat16(r);
    __nv_bfloat16 ll = __float2bfloat16(r - __bfloat162float(hh));
    __nv_bfloat16* dst = g_a3small + (size_t)q * K3 + h * DH + d;
    dst[0] = hh; dst[1024] = hh; dst[2048] = ll;
}

// ---------------- launch ----------------
#define ATTN_SMEM ((4 * 64 * ASTR + 192) * (int)sizeof(float))   /* 70400 B */

extern "C" void kernel_launch(void* const* d_in, const int* in_sizes, int n_in,
                              void* d_out, int out_size) {
    const float* x    = (const float*)d_in[0];
    const float* lat  = (const float*)d_in[1];
    const float* g1   = (const float*)d_in[2];
    const float* b1   = (const float*)d_in[3];
    const float* g2   = (const float*)d_in[4];
    const float* b2   = (const float*)d_in[5];
    const float* Wq   = (const float*)d_in[6];
    const float* Wkv  = (const float*)d_in[7];
    const float* Wout = (const float*)d_in[8];
    const int*   um   = (const int*)d_in[9];
    float* out = (float*)d_out;

    cudaFuncSetAttribute(gemm_qkv,  cudaFuncAttributeMaxDynamicSharedMemorySize, GEMM_SMEM);
    cudaFuncSetAttribute(gemm_out,  cudaFuncAttributeMaxDynamicSharedMemorySize, GEMM_SMEM);
    cudaFuncSetAttribute(attn_part, cudaFuncAttributeMaxDynamicSharedMemorySize, ATTN_SMEM);

    // 1. LayerNorms -> split-bf16 GEMM operands directly
    ln_kernel<<<ROWS_X + ROWS_LAT, 256>>>(x, lat, g1, b1, g2, b2);

    // 2. all weight conversions, one launch
    convW_all<<<4096, dim3(32, 8)>>>(Wq, Wkv, Wout);

    // 3. Q + KV projections, one launch (R9 2-stage GEMM core)
    gemm_qkv<<<KV_TILES + Q_TILES, 256, GEMM_SMEM>>>();

    // 4. attention partials (one block per 64-key subtile) + streaming combine
    attn_part<<<dim3(NSUB, HEADS, B_LAT), 256, ATTN_SMEM>>>(um);
    attn_combine<<<dim3(ROWS_LAT / 4, HEADS), 256>>>(um);

    // 5. output projection
    gemm_out<<<dim3(DD / 128, (ROWS_LAT + 127) / 128), 256, GEMM_SMEM>>>(out);
}

// round 12
// speedup vs baseline: 1.1619x; 1.0485x over previous
#include <cuda_runtime.h>
#include <cuda_bf16.h>
#include <math.h>
#include <stdint.h>

#define DD 1024
#define HEADS 16
#define DH 64
#define B_LAT 9
#define B_X 8
#define N_KV 256
#define N_Q 64
#define KV_PER_B (N_KV + N_Q)       /* 320  */
#define ROWS_X (B_X * N_KV)         /* 2048 */
#define ROWS_LAT (B_LAT * N_Q)      /* 576  */
#define ROWS_KV (B_X * KV_PER_B)    /* 2560 */
#define EPS 1e-5f
#define NSUB 40                     /* 2560/64 key subtiles */
#define NPART40 (B_LAT * HEADS * NSUB)   /* 5760 */
#define K3 3072                     /* split-bf16 extended K = 3*1024 */

// ---------------- scratch (static device globals; no allocation) ----------------
__device__ float g_q[ROWS_LAT * DD];
__device__ float g_kv[ROWS_KV * 2 * DD];
__device__ float g_pO[(size_t)NPART40 * 64 * 64];   /* 94.4 MB */
__device__ float g_pm[NPART40 * 64];
__device__ float g_pl[NPART40 * 64];
// split-bf16 operands: A3 = [Ah | Ah | Al] rows [M,3072]; W3 = [Wh | Wl | Wh] rows [N,3072]
__device__ __nv_bfloat16 g_a3kv[(size_t)ROWS_KV * K3];
__device__ __nv_bfloat16 g_a3small[(size_t)ROWS_LAT * K3];   // lnlat splits, later ao splits
__device__ __nv_bfloat16 g_w3q[(size_t)DD * K3];
__device__ __nv_bfloat16 g_w3kv[(size_t)(2 * DD) * K3];
__device__ __nv_bfloat16 g_w3out[(size_t)DD * K3];

// ---------------- PTX helpers (base ISA only: sm_80-compatible) ----------------
__device__ __forceinline__ uint32_t smem_u32(const void* p) {
    uint32_t a;
    asm("{ .reg .u64 t; cvta.to.shared.u64 t, %1; cvt.u32.u64 %0, t; }" : "=r"(a) : "l"(p));
    return a;
}
__device__ __forceinline__ void cp_async16(uint32_t s, const void* g, int sz) {
    asm volatile("cp.async.cg.shared.global [%0], [%1], 16, %2;"
                 :: "r"(s), "l"(g), "r"(sz) : "memory");
}
#define CP_COMMIT()  asm volatile("cp.async.commit_group;" ::: "memory")
#define CP_WAIT0()   asm volatile("cp.async.wait_group 0;" ::: "memory")

__device__ __forceinline__ void ldm_x4(uint32_t* r, uint32_t a) {
    asm volatile("ldmatrix.sync.aligned.m8n8.x4.shared.b16 {%0,%1,%2,%3}, [%4];"
                 : "=r"(r[0]), "=r"(r[1]), "=r"(r[2]), "=r"(r[3]) : "r"(a));
}
__device__ __forceinline__ void mma_bf16(float* d, const uint32_t* a, uint32_t b0, uint32_t b1) {
    asm volatile("mma.sync.aligned.m16n8k16.row.col.f32.bf16.bf16.f32 "
                 "{%0,%1,%2,%3}, {%4,%5,%6,%7}, {%8,%9}, {%0,%1,%2,%3};"
                 : "+f"(d[0]), "+f"(d[1]), "+f"(d[2]), "+f"(d[3])
                 : "r"(a[0]), "r"(a[1]), "r"(a[2]), "r"(a[3]), "r"(b0), "r"(b1));
}

// store 4 fp32 values as split-bf16 triple at dst[0], dst[1024], dst[2048] (8B stores)
__device__ __forceinline__ void store_split4_A(__nv_bfloat16* dst, float4 v) {
    __nv_bfloat162 H0 = {__float2bfloat16(v.x), __float2bfloat16(v.y)};
    __nv_bfloat162 H1 = {__float2bfloat16(v.z), __float2bfloat16(v.w)};
    __nv_bfloat162 L0 = {__float2bfloat16(v.x - __bfloat162float(H0.x)),
                         __float2bfloat16(v.y - __bfloat162float(H0.y))};
    __nv_bfloat162 L1 = {__float2bfloat16(v.z - __bfloat162float(H1.x)),
                         __float2bfloat16(v.w - __bfloat162float(H1.y))};
    uint2 H = make_uint2(*(uint32_t*)&H0, *(uint32_t*)&H1);
    uint2 L = make_uint2(*(uint32_t*)&L0, *(uint32_t*)&L1);
    *(uint2*)&dst[0]    = H;
    *(uint2*)&dst[1024] = H;
    *(uint2*)&dst[2048] = L;
}

// ---------------- merged LN + weight conversion (one launch, 256 threads) ----------------
// blocks [0, 2624): LayerNorm rows -> split-bf16 A operands
// blocks [2624, 6720): 32x32 weight transpose tiles -> split-bf16 W operands
#define LN_BLKS (ROWS_X + ROWS_LAT)   /* 2624 */
__global__ void ln_convW(const float* __restrict__ x, const float* __restrict__ lat,
                         const float* __restrict__ g1, const float* __restrict__ b1,
                         const float* __restrict__ g2, const float* __restrict__ b2,
                         const float* __restrict__ Wq, const float* __restrict__ Wkv,
                         const float* __restrict__ Wout) {
    __shared__ float shmem[32 * 33];
    int tid = threadIdx.x;
    int blk = blockIdx.x;

    if (blk < LN_BLKS) {
        // ---- LayerNorm path ----
        int row = blk;
        const float *src, *g, *b;
        __nv_bfloat16 *dst0, *dst1 = nullptr;
        if (row < ROWS_X) {
            int bb = row / N_KV, n = row % N_KV;
            src = x + (size_t)row * DD; g = g1; b = b1;
            dst0 = g_a3kv + (size_t)(bb * KV_PER_B + n) * K3;
        } else {
            int lr = row - ROWS_X;
            int bb = lr / N_Q, n = lr % N_Q;
            src = lat + (size_t)lr * DD; g = g2; b = b2;
            dst0 = g_a3small + (size_t)lr * K3;
            if (bb < B_X) dst1 = g_a3kv + (size_t)(bb * KV_PER_B + N_KV + n) * K3;
        }
        float4 v = ((const float4*)src)[tid];
        float s  = v.x + v.y + v.z + v.w;
        float ss = v.x*v.x + v.y*v.y + v.z*v.z + v.w*v.w;
        #pragma unroll
        for (int o = 16; o; o >>= 1) {
            s  += __shfl_xor_sync(0xFFFFFFFFu, s,  o);
            ss += __shfl_xor_sync(0xFFFFFFFFu, ss, o);
        }
        float* sb  = shmem;
        float* ssb = shmem + 8;
        int wid = tid >> 5, lane = tid & 31;
        if (lane == 0) { sb[wid] = s; ssb[wid] = ss; }
        __syncthreads();
        float ts = 0.f, tss = 0.f;
        #pragma unroll
        for (int i = 0; i < 8; i++) { ts += sb[i]; tss += ssb[i]; }
        float mean = ts * (1.0f / DD);
        float var  = tss * (1.0f / DD) - mean * mean;
        float inv  = rsqrtf(var + EPS);
        float4 gg = ((const float4*)g)[tid];
        float4 bb4 = ((const float4*)b)[tid];
        float4 o;
        o.x = (v.x - mean) * inv * gg.x + bb4.x;
        o.y = (v.y - mean) * inv * gg.y + bb4.y;
        o.z = (v.z - mean) * inv * gg.z + bb4.z;
        o.w = (v.w - mean) * inv * gg.w + bb4.w;
        store_split4_A(dst0 + tid * 4, o);
        if (dst1) store_split4_A(dst1 + tid * 4, o);
    } else {
        // ---- weight conversion path: W [1024, N] -> [N, 3072] as [Wh | Wl | Wh] ----
        int t = blk - LN_BLKS;
        const float* W; __nv_bfloat16* dst; int N; int lt;
        if (t < 1024)      { W = Wq;   dst = g_w3q;   N = DD;     lt = t; }
        else if (t < 3072) { W = Wkv;  dst = g_w3kv;  N = 2 * DD; lt = t - 1024; }
        else               { W = Wout; dst = g_w3out; N = DD;     lt = t - 3072; }
        int ntiles_x = N / 32;
        int n0 = (lt % ntiles_x) * 32, k0 = (lt / ntiles_x) * 32;
        float (*tt)[33] = (float(*)[33])shmem;
        int tx = tid & 31, ty = tid >> 5;
        #pragma unroll
        for (int j = 0; j < 4; j++)
            tt[ty + j * 8][tx] = W[(size_t)(k0 + ty + j * 8) * N + n0 + tx];
        __syncthreads();
        #pragma unroll
        for (int j = 0; j < 4; j++) {
            int n = n0 + ty + j * 8, k = k0 + tx;
            float a = tt[tx][ty + j * 8];
            __nv_bfloat16 h = __float2bfloat16(a);
            __nv_bfloat16 l = __float2bfloat16(a - __bfloat162float(h));
            size_t o = (size_t)n * K3 + k;
            dst[o] = h; dst[o + 1024] = l; dst[o + 2048] = h;
        }
    }
}

// ---------------- mma.sync bf16 GEMM core (R9 proven 2-stage, 128-row tiles) ----------------
#define GBK 64
#define KST 72
#define ABUF (128 * KST * 2)
#define STAGE (2 * ABUF)
#define GEMM_SMEM (2 * STAGE)                /* 73728 B */
#define NCH (K3 / GBK)                       /* 48 */

__device__ __forceinline__ void gemm_core(const __nv_bfloat16* __restrict__ A3,
                                          const __nv_bfloat16* __restrict__ B3,
                                          float* __restrict__ C,
                                          int M, int N, int br, int bc,
                                          unsigned char* dynsm) {
    int tid = threadIdx.x, wid = tid >> 5, lane = tid & 31;
    int wm = (wid >> 2) * 64;
    int wn = (wid & 3) * 32;

    auto issue = [&](int kb, int buf) {
        unsigned char* sb = dynsm + buf * STAGE;
        const __nv_bfloat16* Ab = A3 + kb * GBK;
        const __nv_bfloat16* Bb = B3 + (size_t)bc * K3 + kb * GBK;
        #pragma unroll
        for (int j = 0; j < 4; j++) {
            int idx = tid + j * 256;
            int r = idx >> 3, c8 = idx & 7;
            int gr = br + r; int sz = (gr < M) ? 16 : 0;
            if (gr >= M) gr = M - 1;
            cp_async16(smem_u32(sb + (r * KST + c8 * 8) * 2),
                       Ab + (size_t)gr * K3 + c8 * 8, sz);
            cp_async16(smem_u32(sb + ABUF + (r * KST + c8 * 8) * 2),
                       Bb + (size_t)r * K3 + c8 * 8, 16);
        }
        CP_COMMIT();
    };

    float acc[4][4][4] = {};

    issue(0, 0);
    CP_WAIT0();
    __syncthreads();

    for (int kb = 0; kb < NCH; kb++) {
        int cur = kb & 1;
        if (kb + 1 < NCH) issue(kb + 1, cur ^ 1);

        const unsigned char* sA = dynsm + cur * STAGE;
        const unsigned char* sB = sA + ABUF;
        #pragma unroll
        for (int ks = 0; ks < 4; ks++) {
            int k0 = ks * 16;
            uint32_t a[4][4];
            #pragma unroll
            for (int mt = 0; mt < 4; mt++) {
                int arow = wm + mt * 16 + (lane & 15);
                int acol = k0 + (lane >> 4) * 8;
                ldm_x4(a[mt], smem_u32(sA + (arow * KST + acol) * 2));
            }
            uint32_t b[2][4];
            #pragma unroll
            for (int np = 0; np < 2; np++) {
                int nrow = wn + np * 16 + (lane & 7) + ((lane >> 4) << 3);
                int kcol = k0 + ((lane >> 3) & 1) * 8;
                ldm_x4(b[np], smem_u32(sB + (nrow * KST + kcol) * 2));
            }
            #pragma unroll
            for (int mt = 0; mt < 4; mt++)
                #pragma unroll
                for (int nt = 0; nt < 4; nt++)
                    mma_bf16(acc[mt][nt], a[mt], b[nt >> 1][(nt & 1) * 2],
                             b[nt >> 1][(nt & 1) * 2 + 1]);
        }
        if (kb + 1 < NCH) CP_WAIT0();
        __syncthreads();
    }

    #pragma unroll
    for (int mt = 0; mt < 4; mt++) {
        int r0 = br + wm + mt * 16 + (lane >> 2);
        #pragma unroll
        for (int nt = 0; nt < 4; nt++) {
            int c = bc + wn + nt * 8 + (lane & 3) * 2;
            if (r0 < M)
                *(float2*)&C[(size_t)r0 * N + c] = make_float2(acc[mt][nt][0], acc[mt][nt][1]);
            if (r0 + 8 < M)
                *(float2*)&C[(size_t)(r0 + 8) * N + c] = make_float2(acc[mt][nt][2], acc[mt][nt][3]);
        }
    }
}

// ---------------- 64-row-tile GEMM core (for the small M=576 output projection) ----------------
#define ABUF64 (64 * KST * 2)                /* 9216 B */
#define STAGE64 (ABUF64 + ABUF)              /* A 64 rows + B 128 rows = 27648 B */
#define GEMM64_SMEM (2 * STAGE64)            /* 55296 B */

__device__ __forceinline__ void gemm_core64(const __nv_bfloat16* __restrict__ A3,
                                            const __nv_bfloat16* __restrict__ B3,
                                            float* __restrict__ C,
                                            int M, int N, int br, int bc,
                                            unsigned char* dynsm) {
    int tid = threadIdx.x, wid = tid >> 5, lane = tid & 31;
    int wm = (wid >> 2) * 32;     // 2 warp-rows x 32 rows
    int wn = (wid & 3) * 32;

    auto issue = [&](int kb, int buf) {
        unsigned char* sb = dynsm + buf * STAGE64;
        const __nv_bfloat16* Ab = A3 + kb * GBK;
        const __nv_bfloat16* Bb = B3 + (size_t)bc * K3 + kb * GBK;
        // A: 64 rows x 8 float4 = 512 -> 2 per thread
        #pragma unroll
        for (int j = 0; j < 2; j++) {
            int idx = tid + j * 256;
            int r = idx >> 3, c8 = idx & 7;
            int gr = br + r; int sz = (gr < M) ? 16 : 0;
            if (gr >= M) gr = M - 1;
            cp_async16(smem_u32(sb + (r * KST + c8 * 8) * 2),
                       Ab + (size_t)gr * K3 + c8 * 8, sz);
        }
        // B: 128 rows x 8 float4 = 1024 -> 4 per thread
        #pragma unroll
        for (int j = 0; j < 4; j++) {
            int idx = tid + j * 256;
            int r = idx >> 3, c8 = idx & 7;
            cp_async16(smem_u32(sb + ABUF64 + (r * KST + c8 * 8) * 2),
                       Bb + (size_t)r * K3 + c8 * 8, 16);
        }
        CP_COMMIT();
    };

    float acc[2][4][4] = {};

    issue(0, 0);
    CP_WAIT0();
    __syncthreads();

    for (int kb = 0; kb < NCH; kb++) {
        int cur = kb & 1;
        if (kb + 1 < NCH) issue(kb + 1, cur ^ 1);

        const unsigned char* sA = dynsm + cur * STAGE64;
        const unsigned char* sB = sA + ABUF64;
        #pragma unroll
        for (int ks = 0; ks < 4; ks++) {
            int k0 = ks * 16;
            uint32_t a[2][4];
            #pragma unroll
            for (int mt = 0; mt < 2; mt++) {
                int arow = wm + mt * 16 + (lane & 15);
                int acol = k0 + (lane >> 4) * 8;
                ldm_x4(a[mt], smem_u32(sA + (arow * KST + acol) * 2));
            }
            uint32_t b[2][4];
            #pragma unroll
            for (int np = 0; np < 2; np++) {
                int nrow = wn + np * 16 + (lane & 7) + ((lane >> 4) << 3);
                int kcol = k0 + ((lane >> 3) & 1) * 8;
                ldm_x4(b[np], smem_u32(sB + (nrow * KST + kcol) * 2));
            }
            #pragma unroll
            for (int mt = 0; mt < 2; mt++)
                #pragma unroll
                for (int nt = 0; nt < 4; nt++)
                    mma_bf16(acc[mt][nt], a[mt], b[nt >> 1][(nt & 1) * 2],
                             b[nt >> 1][(nt & 1) * 2 + 1]);
        }
        if (kb + 1 < NCH) CP_WAIT0();
        __syncthreads();
    }

    #pragma unroll
    for (int mt = 0; mt < 2; mt++) {
        int r0 = br + wm + mt * 16 + (lane >> 2);
        #pragma unroll
        for (int nt = 0; nt < 4; nt++) {
            int c = bc + wn + nt * 8 + (lane & 3) * 2;
            if (r0 < M)
                *(float2*)&C[(size_t)r0 * N + c] = make_float2(acc[mt][nt][0], acc[mt][nt][1]);
            if (r0 + 8 < M)
                *(float2*)&C[(size_t)(r0 + 8) * N + c] = make_float2(acc[mt][nt][2], acc[mt][nt][3]);
        }
    }
}

// merged Q + KV projection: KV tiles (320) first, then Q tiles (40)
#define KV_TILES 320
#define Q_TILES  40

__global__ __launch_bounds__(256)
void gemm_qkv() {
    extern __shared__ __align__(16) unsigned char dynsm[];
    int bid = blockIdx.x;
    if (bid < KV_TILES) {
        int bx = bid & 15, by = bid >> 4;
        gemm_core(g_a3kv, g_w3kv, g_kv, ROWS_KV, 2 * DD, by * 128, bx * 128, dynsm);
    } else {
        int t = bid - KV_TILES;
        int bx = t & 7, by = t >> 3;
        gemm_core(g_a3small, g_w3q, g_q, ROWS_LAT, DD, by * 128, bx * 128, dynsm);
    }
}

__global__ __launch_bounds__(256)
void gemm_out(float* __restrict__ C) {
    extern __shared__ __align__(16) unsigned char dynsm[];
    gemm_core64(g_a3small, g_w3out, C, ROWS_LAT, DD, blockIdx.y * 64, blockIdx.x * 128, dynsm);
}

// ---------------- attention: one block per 64-key subtile, single-pass softmax ----------------
#define ASTR 68

__global__ __launch_bounds__(256)
void attn_part(const int* __restrict__ um_p) {
    int s  = blockIdx.x;
    int h  = blockIdx.y;
    int qb = blockIdx.z;
    int um = *um_p;
    bool masked = (um != 0) && (qb < B_X);
    if (masked && s >= 5) return;   // whole block exits before any barrier
    int kbase = masked ? (qb * KV_PER_B + s * 64) : (s * 64);

    extern __shared__ float smf[];
    float* Qs = smf;                    // [d][q] pre-scaled
    float* Ks = smf + 64 * ASTR;        // [d][k]
    float* Vs = smf + 2 * 64 * ASTR;    // [k][d]
    float* Ps = smf + 3 * 64 * ASTR;    // [q][k]
    float* mrow = smf + 4 * 64 * ASTR;  // [64]
    float* lrow = mrow + 64;

    int tid = threadIdx.x;
    int ty = tid >> 4, tx = tid & 15;

    #pragma unroll
    for (int it = 0; it < 4; it++) {
        int row = ty + it * 16;
        int col = tx * 4;
        float4 v = *(const float4*)&g_q[(size_t)(qb * 64 + row) * DD + h * DH + col];
        Qs[(col + 0) * ASTR + row] = v.x * 0.125f;
        Qs[(col + 1) * ASTR + row] = v.y * 0.125f;
        Qs[(col + 2) * ASTR + row] = v.z * 0.125f;
        Qs[(col + 3) * ASTR + row] = v.w * 0.125f;
        const float* base = g_kv + (size_t)(kbase + row) * (2 * DD) + h * DH + col;
        float4 kk = *(const float4*)base;
        Ks[(col + 0) * ASTR + row] = kk.x;
        Ks[(col + 1) * ASTR + row] = kk.y;
        Ks[(col + 2) * ASTR + row] = kk.z;
        Ks[(col + 3) * ASTR + row] = kk.w;
        *(float4*)&Vs[row * ASTR + col] = *(const float4*)(base + DD);
    }
    __syncthreads();

    float sacc[4][4] = {};
    #pragma unroll
    for (int d = 0; d < 64; d++) {
        float4 aq = *(const float4*)&Qs[d * ASTR + ty * 4];
        float4 bk = *(const float4*)&Ks[d * ASTR + tx * 4];
        sacc[0][0] += aq.x * bk.x; sacc[0][1] += aq.x * bk.y;
        sacc[0][2] += aq.x * bk.z; sacc[0][3] += aq.x * bk.w;
        sacc[1][0] += aq.y * bk.x; sacc[1][1] += aq.y * bk.y;
        sacc[1][2] += aq.y * bk.z; sacc[1][3] += aq.y * bk.w;
        sacc[2][0] += aq.z * bk.x; sacc[2][1] += aq.z * bk.y;
        sacc[2][2] += aq.z * bk.z; sacc[2][3] += aq.z * bk.w;
        sacc[3][0] += aq.w * bk.x; sacc[3][1] += aq.w * bk.y;
        sacc[3][2] += aq.w * bk.z; sacc[3][3] += aq.w * bk.w;
    }
    #pragma unroll
    for (int i = 0; i < 4; i++)
        #pragma unroll
        for (int j = 0; j < 4; j++)
            Ps[(ty * 4 + i) * ASTR + tx * 4 + j] = sacc[i][j];
    __syncthreads();

    {
        int r = tid >> 2, part = tid & 3;
        float rm = -INFINITY;
        #pragma unroll
        for (int i = 0; i < 16; i++)
            rm = fmaxf(rm, Ps[r * ASTR + part * 16 + i]);
        rm = fmaxf(rm, __shfl_xor_sync(0xFFFFFFFFu, rm, 1));
        rm = fmaxf(rm, __shfl_xor_sync(0xFFFFFFFFu, rm, 2));
        float psum = 0.f;
        #pragma unroll
        for (int i = 0; i < 16; i++) {
            float p = __expf(Ps[r * ASTR + part * 16 + i] - rm);
            Ps[r * ASTR + part * 16 + i] = p;
            psum += p;
        }
        psum += __shfl_xor_sync(0xFFFFFFFFu, psum, 1);
        psum += __shfl_xor_sync(0xFFFFFFFFu, psum, 2);
        if (part == 0) { mrow[r] = rm; lrow[r] = psum; }
    }
    __syncthreads();

    float oacc[4][4] = {};
    #pragma unroll
    for (int k = 0; k < 64; k++) {
        float4 v4 = *(const float4*)&Vs[k * ASTR + tx * 4];
        float p0 = Ps[(ty * 4 + 0) * ASTR + k];
        float p1 = Ps[(ty * 4 + 1) * ASTR + k];
        float p2 = Ps[(ty * 4 + 2) * ASTR + k];
        float p3 = Ps[(ty * 4 + 3) * ASTR + k];
        oacc[0][0] += p0 * v4.x; oacc[0][1] += p0 * v4.y;
        oacc[0][2] += p0 * v4.z; oacc[0][3] += p0 * v4.w;
        oacc[1][0] += p1 * v4.x; oacc[1][1] += p1 * v4.y;
        oacc[1][2] += p1 * v4.z; oacc[1][3] += p1 * v4.w;
        oacc[2][0] += p2 * v4.x; oacc[2][1] += p2 * v4.y;
        oacc[2][2] += p2 * v4.z; oacc[2][3] += p2 * v4.w;
        oacc[3][0] += p3 * v4.x; oacc[3][1] += p3 * v4.y;
        oacc[3][2] += p3 * v4.z; oacc[3][3] += p3 * v4.w;
    }

    int pidx = (qb * HEADS + h) * NSUB + s;
    #pragma unroll
    for (int i = 0; i < 4; i++) {
        float4 o = make_float4(oacc[i][0], oacc[i][1], oacc[i][2], oacc[i][3]);
        *(float4*)&g_pO[((size_t)pidx * 64 + ty * 4 + i) * 64 + tx * 4] = o;
    }
    if (tid < 64) {
        g_pm[pidx * 64 + tid] = mrow[tid];
        g_pl[pidx * 64 + tid] = lrow[tid];
    }
}

// merge partials per (q,h) row: 5 (masked, block qb<8) or 40 (dense); streaming
__global__ __launch_bounds__(256)
void attn_combine(const int* __restrict__ um_p) {
    int q = blockIdx.x * 4 + (threadIdx.x >> 6);
    int h = blockIdx.y;
    int qb = q >> 6, qq = q & 63;
    int um = *um_p;
    bool masked = (um != 0) && (qb < B_X);
    int ns = masked ? 5 : NSUB;
    int d = threadIdx.x & 63;
    int pbase = (qb * HEADS + h) * NSUB;

    float M = -INFINITY;
    for (int c = 0; c < ns; c++)
        M = fmaxf(M, g_pm[(pbase + c) * 64 + qq]);
    float L = 0.f, o = 0.f;
    for (int c = 0; c < ns; c++) {
        float e = __expf(g_pm[(pbase + c) * 64 + qq] - M);
        L += g_pl[(pbase + c) * 64 + qq] * e;
        o += g_pO[((size_t)(pbase + c) * 64 + qq) * 64 + d] * e;
    }
    float r = o / L;
    __nv_bfloat16 hh = __float2bfloat16(r);
    __nv_bfloat16 ll = __float2bfloat16(r - __bfloat162float(hh));
    __nv_bfloat16* dst = g_a3small + (size_t)q * K3 + h * DH + d;
    dst[0] = hh; dst[1024] = hh; dst[2048] = ll;
}

// ---------------- launch ----------------
#define ATTN_SMEM ((4 * 64 * ASTR + 192) * (int)sizeof(float))   /* 70400 B */

extern "C" void kernel_launch(void* const* d_in, const int* in_sizes, int n_in,
                              void* d_out, int out_size) {
    const float* x    = (const float*)d_in[0];
    const float* lat  = (const float*)d_in[1];
    const float* g1   = (const float*)d_in[2];
    const float* b1   = (const float*)d_in[3];
    const float* g2   = (const float*)d_in[4];
    const float* b2   = (const float*)d_in[5];
    const float* Wq   = (const float*)d_in[6];
    const float* Wkv  = (const float*)d_in[7];
    const float* Wout = (const float*)d_in[8];
    const int*   um   = (const int*)d_in[9];
    float* out = (float*)d_out;

    cudaFuncSetAttribute(gemm_qkv,  cudaFuncAttributeMaxDynamicSharedMemorySize, GEMM_SMEM);
    cudaFuncSetAttribute(gemm_out,  cudaFuncAttributeMaxDynamicSharedMemorySize, GEMM64_SMEM);
    cudaFuncSetAttribute(attn_part, cudaFuncAttributeMaxDynamicSharedMemorySize, ATTN_SMEM);

    // 1. LayerNorm + all weight conversions in ONE launch
    ln_convW<<<LN_BLKS + 4096, 256>>>(x, lat, g1, b1, g2, b2, Wq, Wkv, Wout);

    // 2. Q + KV projections, one launch (R9 2-stage GEMM core)
    gemm_qkv<<<KV_TILES + Q_TILES, 256, GEMM_SMEM>>>();

    // 3. attention partials (one block per 64-key subtile) + streaming combine
    attn_part<<<dim3(NSUB, HEADS, B_LAT), 256, ATTN_SMEM>>>(um);
    attn_combine<<<dim3(ROWS_LAT / 4, HEADS), 256>>>(um);

    // 4. output projection (64-row tiles, 72 CTAs)
    gemm_out<<<dim3(DD / 128, ROWS_LAT / 64), 256, GEMM64_SMEM>>>(out);
}